// round 8
// baseline (speedup 1.0000x reference)
#include <cuda_runtime.h>

// Problem constants (from reference setup_inputs)
#define NB 8
#define NC 64
#define HH 128
#define WW 128
#define EH 64
#define EW 64
#define THETA 10.0f

// ---- weights kernel config (unchanged) ----
#define WROWS 4
#define WTBLK 128
#define WNROW (HH / WROWS)             // 32

// ---- apply kernel config ----
#define CSPB 8                         // channels per block
#define NCGRP (NC / CSPB)              // 8
#define AROWS 2                        // rows per apply block (4 warps = 2 rows x 2 halves)
#define ANROW (HH / AROWS)             // 64
#define ATBLK 128

// Precomputed normalized weights: [n][y][k][x], k = 0..8 tap index.
// 8*128*9*128 floats = 4.72 MB (static device scratch; no runtime alloc).
__device__ float g_wbuf[NB * HH * 9 * WW];

// ---------------------------------------------------------------------------
// Kernel 1: per-pixel softmax weights from bilinear-upsampled edge.
// Boundary zero-padding of the MASK taps is folded into the stored weights
// (padded tap contributes m=0, identical to zero weight; softmax denominator
// already includes all 9 exps). Stored per-pixel, so the apply kernel's
// thread mapping is independent of this one.
// ---------------------------------------------------------------------------
__global__ __launch_bounds__(WTBLK)
void geg_weights_kernel(const float* __restrict__ edge)
{
    const int t    = threadIdx.x;
    const int warp = t >> 5;
    const int lane = t & 31;
    const int y    = blockIdx.x * WROWS + warp;  // 0..127
    const int n    = blockIdx.y;                 // 0..7
    const int x0   = lane * 4;

    const float* eptr = edge + n * (EH * EW);
    const float sc = 63.0f / 127.0f;   // (EH-1)/(HH-1), align_corners

    float er[3][6];
    #pragma unroll
    for (int r = 0; r < 3; r++) {
        const int gy = y - 1 + r;
        float4 ev = make_float4(0.f, 0.f, 0.f, 0.f);
        if (gy >= 0 && gy < HH) {
            const float ys = (float)gy * sc;
            const int   yi = (int)ys;
            const float wy = ys - (float)yi;
            const int   y1 = min(yi + 1, EH - 1);
            const float* r0 = eptr + yi * EW;
            const float* r1 = eptr + y1 * EW;
            float v[4];
            #pragma unroll
            for (int p = 0; p < 4; p++) {
                const int   gx = x0 + p;
                const float xs = (float)gx * sc;
                const int   xi = (int)xs;
                const float wx = xs - (float)xi;
                const int   x1 = min(xi + 1, EW - 1);
                const float a  = r0[xi];
                const float b  = r0[x1];
                const float c0 = r1[xi];
                const float d  = r1[x1];
                const float top = a  + (b  - a ) * wx;
                const float bot = c0 + (d  - c0) * wx;
                v[p] = top + (bot - top) * wy;
            }
            ev = make_float4(v[0], v[1], v[2], v[3]);
        }
        float left  = __shfl_up_sync(0xffffffffu, ev.w, 1);
        float right = __shfl_down_sync(0xffffffffu, ev.x, 1);
        if (lane == 0)  left  = 0.f;
        if (lane == 31) right = 0.f;
        er[r][0] = left; er[r][1] = ev.x; er[r][2] = ev.y;
        er[r][3] = ev.z; er[r][4] = ev.w; er[r][5] = right;
    }

    float w[4][9];
    #pragma unroll
    for (int p = 0; p < 4; p++) {
        const float ec = er[1][p + 1];
        float s = 0.f;
        #pragma unroll
        for (int k = 0; k < 9; k++) {
            const float d  = ec - er[k / 3][p + (k % 3)];
            const float pw = __expf(-THETA * d * d);
            w[p][k] = pw;
            s += pw;
        }
        const float rs = 1.f / s;
        #pragma unroll
        for (int k = 0; k < 9; k++) w[p][k] *= rs;
    }

    if (y == 0) {
        #pragma unroll
        for (int p = 0; p < 4; p++) { w[p][0] = 0.f; w[p][1] = 0.f; w[p][2] = 0.f; }
    }
    if (y == HH - 1) {
        #pragma unroll
        for (int p = 0; p < 4; p++) { w[p][6] = 0.f; w[p][7] = 0.f; w[p][8] = 0.f; }
    }
    if (lane == 0)  { w[0][0] = 0.f; w[0][3] = 0.f; w[0][6] = 0.f; }
    if (lane == 31) { w[3][2] = 0.f; w[3][5] = 0.f; w[3][8] = 0.f; }

    float* wb = g_wbuf + (n * HH + y) * (9 * WW) + x0;
    #pragma unroll
    for (int k = 0; k < 9; k++)
        *reinterpret_cast<float4*>(wb + k * WW) =
            make_float4(w[0][k], w[1][k], w[2][k], w[3][k]);
}

// ---------------------------------------------------------------------------
// Kernel 2: apply weights across channels. 2 pixels per lane (float2) to
// halve per-thread register state (18 weight regs) and maximize occupancy.
// Warp covers half a row; the x=63/64 seam is patched by one predicated
// scalar load per row. No smem, no barriers.
// ---------------------------------------------------------------------------
__global__ __launch_bounds__(ATBLK, 11)
void geg_apply_kernel(const float* __restrict__ mask,
                      float* __restrict__ out)
{
    const int t    = threadIdx.x;
    const int warp = t >> 5;
    const int lane = t & 31;
    const int half = warp & 1;         // which half-row
    const int rloc = warp >> 1;        // 0..1 local row

    const int y    = blockIdx.x * AROWS + rloc;   // 0..127
    const int cgrp = blockIdx.y;                  // 0..7
    const int n    = blockIdx.z;                  // 0..7

    const int x0 = half * 64 + lane * 2;          // first of 2 pixels

    const int img  = HH * WW;
    const int base = (n * NC + cgrp * CSPB) * img;
    const float* mp = mask + base;
    float*       op = out  + base;

    // Clamped row offsets (OOB rows carry zero weight).
    const int off0 = max(y - 1, 0)      * WW + x0;
    const int off1 = y                  * WW + x0;
    const int off2 = min(y + 1, HH - 1) * WW + x0;
    const int offs = y * WW + x0;

    // Seam fixup: lane0 of half 1 needs x0-1 (=63); lane31 of half 0 needs
    // x0+2 (=64). Single predicated scalar load per row covers both cases.
    const bool needL = (lane == 0)  && (half == 1);
    const bool needR = (lane == 31) && (half == 0);
    const bool needF = needL || needR;
    const int  fixd  = needL ? -1 : 2;
    const int  foff0 = off0 + fixd;
    const int  foff1 = off1 + fixd;
    const int  foff2 = off2 + fixd;

    // Load 18 precomputed weights (9 coalesced float2 loads).
    float w[2][9];
    {
        const float* wb = g_wbuf + (n * HH + y) * (9 * WW) + x0;
        #pragma unroll
        for (int k = 0; k < 9; k++) {
            float2 v = *reinterpret_cast<const float2*>(wb + k * WW);
            w[0][k] = v.x; w[1][k] = v.y;
        }
    }

    #pragma unroll 1
    for (int c = 0; c < CSPB; c++) {
        float2 m0 = *reinterpret_cast<const float2*>(mp + off0);
        float2 m1 = *reinterpret_cast<const float2*>(mp + off1);
        float2 m2 = *reinterpret_cast<const float2*>(mp + off2);

        float f0 = 0.f, f1 = 0.f, f2 = 0.f;
        if (needF) {
            f0 = __ldg(mp + foff0);
            f1 = __ldg(mp + foff1);
            f2 = __ldg(mp + foff2);
        }

        float l0 = __shfl_up_sync(0xffffffffu, m0.y, 1);
        float r0 = __shfl_down_sync(0xffffffffu, m0.x, 1);
        float l1 = __shfl_up_sync(0xffffffffu, m1.y, 1);
        float r1 = __shfl_down_sync(0xffffffffu, m1.x, 1);
        float l2 = __shfl_up_sync(0xffffffffu, m2.y, 1);
        float r2 = __shfl_down_sync(0xffffffffu, m2.x, 1);
        if (needL) { l0 = f0; l1 = f1; l2 = f2; }   // seam: true x-1 value
        if (needR) { r0 = f0; r1 = f1; r2 = f2; }   // seam: true x+2 value
        // Image-edge lanes (x=0 left / x=127 right) carry ZERO weight, so the
        // garbage shuffle values there are harmless.

        // pixel0 taps: l, m.x, m.y ; pixel1 taps: m.x, m.y, r
        float a0, a1;
        a0  = w[0][0] * l0;   a1  = w[1][0] * m0.x;
        a0 = fmaf(w[0][1], m0.x, a0);  a1 = fmaf(w[1][1], m0.y, a1);
        a0 = fmaf(w[0][2], m0.y, a0);  a1 = fmaf(w[1][2], r0,   a1);
        a0 = fmaf(w[0][3], l1,   a0);  a1 = fmaf(w[1][3], m1.x, a1);
        a0 = fmaf(w[0][4], m1.x, a0);  a1 = fmaf(w[1][4], m1.y, a1);
        a0 = fmaf(w[0][5], m1.y, a0);  a1 = fmaf(w[1][5], r1,   a1);
        a0 = fmaf(w[0][6], l2,   a0);  a1 = fmaf(w[1][6], m2.x, a1);
        a0 = fmaf(w[0][7], m2.x, a0);  a1 = fmaf(w[1][7], m2.y, a1);
        a0 = fmaf(w[0][8], m2.y, a0);  a1 = fmaf(w[1][8], r2,   a1);

        *reinterpret_cast<float2*>(op + offs) = make_float2(a0, a1);

        mp += img;
        op += img;
    }
}

extern "C" void kernel_launch(void* const* d_in, const int* in_sizes, int n_in,
                              void* d_out, int out_size)
{
    const float* mask = (const float*)d_in[0];
    const float* edge = (const float*)d_in[1];
    if (n_in >= 2 && in_sizes[0] < in_sizes[1]) {   // defensive swap by size
        const float* tmp = mask; mask = edge; edge = tmp;
    }
    float* out = (float*)d_out;

    dim3 wgrid(WNROW, NB);              // 32 x 8 = 256 blocks
    geg_weights_kernel<<<wgrid, WTBLK>>>(edge);

    dim3 agrid(ANROW, NCGRP, NB);       // 64 x 8 x 8 = 4096 blocks
    geg_apply_kernel<<<agrid, ATBLK>>>(mask, out);
}

// round 9
// speedup vs baseline: 1.6560x; 1.6560x over previous
#include <cuda_runtime.h>

// Problem constants (from reference setup_inputs)
#define NB 8
#define NC 64
#define HH 128
#define WW 128
#define EH 64
#define EW 64
#define THETA 10.0f

#define CSPB 8                         // channels per block (apply kernel)
#define NCGRP (NC / CSPB)              // 8 channel groups
#define ROWS_PER_BLK 4                 // 4 warps -> 4 rows
#define NROWBLK (HH / ROWS_PER_BLK)    // 32
#define TBLK (ROWS_PER_BLK * 32)       // 128 threads

// Precomputed normalized weights: [n][y][k][x], k = 0..8 tap index.
// 8*128*9*128 floats = 4.72 MB (static device scratch; no runtime alloc).
__device__ float g_wbuf[NB * HH * 9 * WW];

// ---------------------------------------------------------------------------
// Kernel 1: per-pixel softmax weights from bilinear-upsampled edge.
// Boundary zero-padding of the MASK taps is folded into the stored weights
// (padded tap contributes m=0, identical to zero weight; softmax denominator
// already includes all 9 exps).
// ---------------------------------------------------------------------------
__global__ __launch_bounds__(TBLK)
void geg_weights_kernel(const float* __restrict__ edge)
{
    const int t    = threadIdx.x;
    const int warp = t >> 5;
    const int lane = t & 31;
    const int y    = blockIdx.x * ROWS_PER_BLK + warp;  // 0..127
    const int n    = blockIdx.y;                        // 0..7
    const int x0   = lane * 4;

    const float* eptr = edge + n * (EH * EW);
    const float sc = 63.0f / 127.0f;   // (EH-1)/(HH-1), align_corners

    float er[3][6];
    #pragma unroll
    for (int r = 0; r < 3; r++) {
        const int gy = y - 1 + r;
        float4 ev = make_float4(0.f, 0.f, 0.f, 0.f);
        if (gy >= 0 && gy < HH) {
            const float ys = (float)gy * sc;
            const int   yi = (int)ys;
            const float wy = ys - (float)yi;
            const int   y1 = min(yi + 1, EH - 1);
            const float* r0 = eptr + yi * EW;
            const float* r1 = eptr + y1 * EW;
            float v[4];
            #pragma unroll
            for (int p = 0; p < 4; p++) {
                const int   gx = x0 + p;
                const float xs = (float)gx * sc;
                const int   xi = (int)xs;
                const float wx = xs - (float)xi;
                const int   x1 = min(xi + 1, EW - 1);
                const float a  = r0[xi];
                const float b  = r0[x1];
                const float c0 = r1[xi];
                const float d  = r1[x1];
                const float top = a  + (b  - a ) * wx;
                const float bot = c0 + (d  - c0) * wx;
                v[p] = top + (bot - top) * wy;
            }
            ev = make_float4(v[0], v[1], v[2], v[3]);
        }
        float left  = __shfl_up_sync(0xffffffffu, ev.w, 1);
        float right = __shfl_down_sync(0xffffffffu, ev.x, 1);
        if (lane == 0)  left  = 0.f;
        if (lane == 31) right = 0.f;
        er[r][0] = left; er[r][1] = ev.x; er[r][2] = ev.y;
        er[r][3] = ev.z; er[r][4] = ev.w; er[r][5] = right;
    }

    float w[4][9];
    #pragma unroll
    for (int p = 0; p < 4; p++) {
        const float ec = er[1][p + 1];
        float s = 0.f;
        #pragma unroll
        for (int k = 0; k < 9; k++) {
            const float d  = ec - er[k / 3][p + (k % 3)];
            const float pw = __expf(-THETA * d * d);
            w[p][k] = pw;
            s += pw;
        }
        const float rs = 1.f / s;
        #pragma unroll
        for (int k = 0; k < 9; k++) w[p][k] *= rs;
    }

    if (y == 0) {
        #pragma unroll
        for (int p = 0; p < 4; p++) { w[p][0] = 0.f; w[p][1] = 0.f; w[p][2] = 0.f; }
    }
    if (y == HH - 1) {
        #pragma unroll
        for (int p = 0; p < 4; p++) { w[p][6] = 0.f; w[p][7] = 0.f; w[p][8] = 0.f; }
    }
    if (lane == 0)  { w[0][0] = 0.f; w[0][3] = 0.f; w[0][6] = 0.f; }
    if (lane == 31) { w[3][2] = 0.f; w[3][5] = 0.f; w[3][8] = 0.f; }

    float* wb = g_wbuf + (n * HH + y) * (9 * WW) + x0;
    #pragma unroll
    for (int k = 0; k < 9; k++)
        *reinterpret_cast<float4*>(wb + k * WW) =
            make_float4(w[0][k], w[1][k], w[2][k], w[3][k]);
}

// ---------------------------------------------------------------------------
// Kernel 2: apply weights across channels (R4 structure). One warp per row;
// lane handles 4 pixels via float4; no smem, no barriers. 64-reg cap gives
// 8 blocks/SM; streaming stores keep the mask L2-resident.
// ---------------------------------------------------------------------------
__global__ __launch_bounds__(TBLK, 8)
void geg_apply_kernel(const float* __restrict__ mask,
                      float* __restrict__ out)
{
    const int t    = threadIdx.x;
    const int warp = t >> 5;
    const int lane = t & 31;

    const int rowblk = blockIdx.x;     // 0..31
    const int cgrp   = blockIdx.y;     // 0..7
    const int n      = blockIdx.z;     // 0..7

    const int y  = rowblk * ROWS_PER_BLK + warp;
    const int x0 = lane * 4;

    // 32-bit offsets everywhere (4.19M elements, fits easily).
    const int img  = HH * WW;
    const int base = (n * NC + cgrp * CSPB) * img;
    const float* mp = mask + base;
    float*       op = out  + base;

    // Clamped row offsets (OOB rows carry zero weight).
    const int off0 = max(y - 1, 0)      * WW + x0;
    const int off1 = y                  * WW + x0;
    const int off2 = min(y + 1, HH - 1) * WW + x0;

    // Load the 36 precomputed weights (9 coalesced float4 loads).
    float w[4][9];
    {
        const float* wb = g_wbuf + (n * HH + y) * (9 * WW) + x0;
        #pragma unroll
        for (int k = 0; k < 9; k++) {
            float4 v = *reinterpret_cast<const float4*>(wb + k * WW);
            w[0][k] = v.x; w[1][k] = v.y; w[2][k] = v.z; w[3][k] = v.w;
        }
    }

    #pragma unroll 2
    for (int c = 0; c < CSPB; c++) {
        float4 m0 = *reinterpret_cast<const float4*>(mp + off0);
        float4 m1 = *reinterpret_cast<const float4*>(mp + off1);
        float4 m2 = *reinterpret_cast<const float4*>(mp + off2);

        float mr[3][6];
        {
            float l0 = __shfl_up_sync(0xffffffffu, m0.w, 1);
            float r0 = __shfl_down_sync(0xffffffffu, m0.x, 1);
            float l1 = __shfl_up_sync(0xffffffffu, m1.w, 1);
            float r1 = __shfl_down_sync(0xffffffffu, m1.x, 1);
            float l2 = __shfl_up_sync(0xffffffffu, m2.w, 1);
            float r2 = __shfl_down_sync(0xffffffffu, m2.x, 1);
            mr[0][0]=l0; mr[0][1]=m0.x; mr[0][2]=m0.y; mr[0][3]=m0.z; mr[0][4]=m0.w; mr[0][5]=r0;
            mr[1][0]=l1; mr[1][1]=m1.x; mr[1][2]=m1.y; mr[1][3]=m1.z; mr[1][4]=m1.w; mr[1][5]=r1;
            mr[2][0]=l2; mr[2][1]=m2.x; mr[2][2]=m2.y; mr[2][3]=m2.z; mr[2][4]=m2.w; mr[2][5]=r2;
        }

        float a[4];
        #pragma unroll
        for (int p = 0; p < 4; p++) {
            float s = 0.f;
            #pragma unroll
            for (int k = 0; k < 9; k++)
                s = fmaf(w[p][k], mr[k / 3][p + (k % 3)], s);
            a[p] = s;
        }

        // Streaming store: evict-first so output lines don't displace the
        // L2-resident mask.
        __stcs(reinterpret_cast<float4*>(op + off1),
               make_float4(a[0], a[1], a[2], a[3]));

        mp += img;
        op += img;
    }
}

extern "C" void kernel_launch(void* const* d_in, const int* in_sizes, int n_in,
                              void* d_out, int out_size)
{
    const float* mask = (const float*)d_in[0];
    const float* edge = (const float*)d_in[1];
    if (n_in >= 2 && in_sizes[0] < in_sizes[1]) {   // defensive swap by size
        const float* tmp = mask; mask = edge; edge = tmp;
    }
    float* out = (float*)d_out;

    dim3 wgrid(NROWBLK, NB);            // 32 x 8 = 256 blocks
    geg_weights_kernel<<<wgrid, TBLK>>>(edge);

    dim3 agrid(NROWBLK, NCGRP, NB);     // 32 x 8 x 8 = 2048 blocks
    geg_apply_kernel<<<agrid, TBLK>>>(mask, out);
}